// round 3
// baseline (speedup 1.0000x reference)
#include <cuda_runtime.h>
#include <cuda_bf16.h>

// LinearMPC: u <- clip(G u + c), 100 iters, G = I - 0.01 H  (512x512), batch 2048.
// Batch rows are independent -> one persistent pass per CTA, no inter-CTA sync.

#define NX 8
#define NU 8
#define NHOR 64
#define MDIM 512           // N*NU
#define BATCH 2048
#define NITER 100
#define ROWS 16            // batch rows per CTA
#define CTAS (BATCH / ROWS)   // 128
#define THREADS 512        // 128 col-threads x 4 row-groups
#define XREF_STRIDE ((NHOR + 1) * NX)  // 520

// Precomputed G^T layout: g_G[k*512 + m] = (k==m) - 0.01*H[m*512 + k]
__device__ float g_G[MDIM * MDIM];

__global__ void init_G_kernel(const float* __restrict__ H) {
    int k = blockIdx.x;        // 0..511
    int m = threadIdx.x;       // 0..511
    float v = -0.01f * H[m * MDIM + k];
    if (k == m) v += 1.0f;
    g_G[k * MDIM + m] = v;
}

__device__ __forceinline__ unsigned long long pack_dup(float x) {
    unsigned long long r;
    asm("mov.b64 %0, {%1, %1};" : "=l"(r) : "f"(x));
    return r;
}
__device__ __forceinline__ unsigned long long pack2(float lo, float hi) {
    unsigned long long r;
    asm("mov.b64 %0, {%1, %2};" : "=l"(r) : "f"(lo), "f"(hi));
    return r;
}
__device__ __forceinline__ void unpack2(unsigned long long v, float& lo, float& hi) {
    asm("mov.b64 {%0, %1}, %2;" : "=f"(lo), "=f"(hi) : "l"(v));
}
// d = a*b + c on packed f32x2 (Blackwell packed fp32 FMA: 2x fma-pipe throughput)
__device__ __forceinline__ unsigned long long fma2(unsigned long long a,
                                                   unsigned long long b,
                                                   unsigned long long c) {
    unsigned long long d;
    asm("fma.rn.f32x2 %0, %1, %2, %3;" : "=l"(d) : "l"(a), "l"(b), "l"(c));
    return d;
}
__device__ __forceinline__ float clip1(float x) {
    return fminf(fmaxf(x, -1.0f), 1.0f);
}

extern "C" __global__ void __launch_bounds__(THREADS, 1)
mpc_kernel(const float* __restrict__ xref,
           const float* __restrict__ Phi,
           const float* __restrict__ Q,
           float* __restrict__ out) {
    extern __shared__ float smem[];   // ping-pong u: 2 * 16 * 512 floats = 64 KB
    float* ubuf = smem;               // ubuf[buf*8192 + row*512 + k]

    const int tid = threadIdx.x;
    const int ct  = tid & 127;        // column-thread: owns cols m0..m0+3
    const int rg  = tid >> 7;         // row group 0..3: owns rows rg*4..rg*4+3
    const int m0  = ct * 4;
    const int k_blk = m0 >> 3;        // horizon index k for these 4 cols (i0 in {0,4})
    const int i0    = m0 & 7;

    // ---------------- Phase 1: c[rr][ii] = 0.02 * (Phi[k] Q dx_b)[i0+ii] ----------------
    float c[4][4];
    {
        // Phi rows i0..i0+3 of block k_blk
        float Pr[4][8];
#pragma unroll
        for (int ii = 0; ii < 4; ++ii)
#pragma unroll
            for (int j = 0; j < 8; ++j)
                Pr[ii][j] = Phi[k_blk * 64 + (i0 + ii) * 8 + j];

        float Qr[8][8];
#pragma unroll
        for (int j = 0; j < 8; ++j)
#pragma unroll
            for (int l = 0; l < 8; ++l)
                Qr[j][l] = Q[j * 8 + l];

#pragma unroll
        for (int rr = 0; rr < 4; ++rr) {
            int b = blockIdx.x * ROWS + rg * 4 + rr;
            const float* xr = xref + (long)b * XREF_STRIDE;
            float dx[8];
#pragma unroll
            for (int l = 0; l < 8; ++l)
                dx[l] = xr[k_blk * 8 + l] - xr[l];
            float qdx[8];
#pragma unroll
            for (int j = 0; j < 8; ++j) {
                float s = 0.0f;
#pragma unroll
                for (int l = 0; l < 8; ++l) s += Qr[j][l] * dx[l];
                qdx[j] = s;
            }
#pragma unroll
            for (int ii = 0; ii < 4; ++ii) {
                float s = 0.0f;
#pragma unroll
                for (int j = 0; j < 8; ++j) s += Pr[ii][j] * qdx[j];
                c[rr][ii] = 0.02f * s;
            }
        }
    }

    // pack c into f32x2 accumulator seeds
    unsigned long long c0[4], c1[4];
#pragma unroll
    for (int rr = 0; rr < 4; ++rr) {
        c0[rr] = pack2(c[rr][0], c[rr][1]);
        c1[rr] = pack2(c[rr][2], c[rr][3]);
    }

    // zero u buffer 0
    for (int idx = tid; idx < ROWS * MDIM; idx += THREADS)
        ubuf[idx] = 0.0f;
    __syncthreads();

    const ulonglong2* __restrict__ G2 = reinterpret_cast<const ulonglong2*>(g_G);

    int cur = 0;
    for (int it = 0; it < NITER; ++it) {
        unsigned long long a0[4], a1[4];
#pragma unroll
        for (int rr = 0; rr < 4; ++rr) { a0[rr] = c0[rr]; a1[rr] = c1[rr]; }

        const float* ub = ubuf + cur * (ROWS * MDIM) + (rg * 4) * MDIM;

#pragma unroll 2
        for (int k = 0; k < MDIM; k += 4) {
            // G rows k..k+3, cols m0..m0+3 (coalesced LDG.128 as packed pairs)
            ulonglong2 gk0 = G2[(k + 0) * 128 + ct];
            ulonglong2 gk1 = G2[(k + 1) * 128 + ct];
            ulonglong2 gk2 = G2[(k + 2) * 128 + ct];
            ulonglong2 gk3 = G2[(k + 3) * 128 + ct];
#pragma unroll
            for (int rr = 0; rr < 4; ++rr) {
                float4 uf = *reinterpret_cast<const float4*>(ub + rr * MDIM + k);
                unsigned long long u0 = pack_dup(uf.x);
                a0[rr] = fma2(gk0.x, u0, a0[rr]);
                a1[rr] = fma2(gk0.y, u0, a1[rr]);
                unsigned long long u1 = pack_dup(uf.y);
                a0[rr] = fma2(gk1.x, u1, a0[rr]);
                a1[rr] = fma2(gk1.y, u1, a1[rr]);
                unsigned long long u2 = pack_dup(uf.z);
                a0[rr] = fma2(gk2.x, u2, a0[rr]);
                a1[rr] = fma2(gk2.y, u2, a1[rr]);
                unsigned long long u3 = pack_dup(uf.w);
                a0[rr] = fma2(gk3.x, u3, a0[rr]);
                a1[rr] = fma2(gk3.y, u3, a1[rr]);
            }
        }

        // clip + write to the other buffer
        int nxt = cur ^ 1;
        float* uw = ubuf + nxt * (ROWS * MDIM) + (rg * 4) * MDIM;
#pragma unroll
        for (int rr = 0; rr < 4; ++rr) {
            float r0, r1, r2, r3;
            unpack2(a0[rr], r0, r1);
            unpack2(a1[rr], r2, r3);
            float4 w;
            w.x = clip1(r0); w.y = clip1(r1); w.z = clip1(r2); w.w = clip1(r3);
            *reinterpret_cast<float4*>(uw + rr * MDIM + m0) = w;
        }
        __syncthreads();
        cur = nxt;
    }

    // write result (coalesced)
    const float* uf = ubuf + cur * (ROWS * MDIM);
    float* ob = out + (long)blockIdx.x * (ROWS * MDIM);
    for (int idx = tid; idx < ROWS * MDIM; idx += THREADS)
        ob[idx] = uf[idx];
}

extern "C" void kernel_launch(void* const* d_in, const int* in_sizes, int n_in,
                              void* d_out, int out_size) {
    // inputs: x0 (unused), xref, H, Phi, Q
    const float* xref = (const float*)d_in[1];
    const float* H    = (const float*)d_in[2];
    const float* Phi  = (const float*)d_in[3];
    const float* Q    = (const float*)d_in[4];
    float* out = (float*)d_out;

    cudaFuncSetAttribute(mpc_kernel,
                         cudaFuncAttributeMaxDynamicSharedMemorySize, 65536);

    init_G_kernel<<<MDIM, MDIM>>>(H);
    mpc_kernel<<<CTAS, THREADS, 65536>>>(xref, Phi, Q, out);
}

// round 4
// speedup vs baseline: 2.0409x; 2.0409x over previous
#include <cuda_runtime.h>
#include <cuda_bf16.h>

// LinearMPC: u <- clip(G u + c), 100 iters, G = I - 0.01 H (512x512), batch 2048.
// R3: zero-redundancy G loads (1 column-pair per thread x all CTA rows),
//     148 CTAs x 14 rows (load balanced), c in registers, iter-1 skipped.

#define MDIM 512
#define BATCH 2048
#define ROWS 14
#define CTAS 148
#define THREADS 256
#define XREF_STRIDE 520          // (64+1)*8
#define SMEM_U (ROWS * MDIM)     // floats per u buffer

// G layout: g_G[k*512 + m] = (k==m) - 0.01*H[m*512 + k]
__device__ float g_G[MDIM * MDIM];

__global__ void init_G_kernel(const float* __restrict__ H) {
    int k = blockIdx.x;
    int m = threadIdx.x;
    float v = -0.01f * H[m * MDIM + k];
    if (k == m) v += 1.0f;
    g_G[k * MDIM + m] = v;
}

__device__ __forceinline__ unsigned long long pack_dup(float x) {
    unsigned long long r;
    asm("mov.b64 %0, {%1, %1};" : "=l"(r) : "f"(x));
    return r;
}
__device__ __forceinline__ unsigned long long pack2(float lo, float hi) {
    unsigned long long r;
    asm("mov.b64 %0, {%1, %2};" : "=l"(r) : "f"(lo), "f"(hi));
    return r;
}
__device__ __forceinline__ void unpack2(unsigned long long v, float& lo, float& hi) {
    asm("mov.b64 {%0, %1}, %2;" : "=f"(lo), "=f"(hi) : "l"(v));
}
__device__ __forceinline__ unsigned long long fma2(unsigned long long a,
                                                   unsigned long long b,
                                                   unsigned long long c) {
    unsigned long long d;
    asm("fma.rn.f32x2 %0, %1, %2, %3;" : "=l"(d) : "l"(a), "l"(b), "l"(c));
    return d;
}
__device__ __forceinline__ float clip1(float x) {
    return fminf(fmaxf(x, -1.0f), 1.0f);
}

extern "C" __global__ void __launch_bounds__(THREADS, 1)
mpc_kernel(const float* __restrict__ xref,
           const float* __restrict__ Phi,
           const float* __restrict__ Q,
           float* __restrict__ out) {
    extern __shared__ float smem[];   // ping-pong u: 2 * 14 * 512 floats = 56 KB
    float* ubuf = smem;

    const int tid = threadIdx.x;
    const int m0  = tid * 2;               // this thread's 2 columns
    const int k_blk = m0 >> 3;             // horizon block for both cols (same block)
    const int i0    = m0 & 7;              // i0 in {0,2,4,6}
    const int row0  = blockIdx.x * ROWS;   // global batch row start (clamped below)

    // ---- Phase 1: c[r] = 0.02 * (Phi[k_blk] Q dx_b)[i0 .. i0+1], packed f32x2 ----
    unsigned long long c2[ROWS];
    {
        float Pr[2][8];
#pragma unroll
        for (int ii = 0; ii < 2; ++ii)
#pragma unroll
            for (int j = 0; j < 8; ++j)
                Pr[ii][j] = Phi[k_blk * 64 + (i0 + ii) * 8 + j];

        float Qr[8][8];
#pragma unroll
        for (int j = 0; j < 8; ++j)
#pragma unroll
            for (int l = 0; l < 8; ++l)
                Qr[j][l] = Q[j * 8 + l];

#pragma unroll
        for (int r = 0; r < ROWS; ++r) {
            int b = row0 + r;
            if (b > BATCH - 1) b = BATCH - 1;          // tail clamp (idempotent)
            const float* xr = xref + (long)b * XREF_STRIDE;
            float dx[8];
#pragma unroll
            for (int l = 0; l < 8; ++l)
                dx[l] = xr[k_blk * 8 + l] - xr[l];
            float qdx[8];
#pragma unroll
            for (int j = 0; j < 8; ++j) {
                float s = 0.0f;
#pragma unroll
                for (int l = 0; l < 8; ++l) s += Qr[j][l] * dx[l];
                qdx[j] = s;
            }
            float cv[2];
#pragma unroll
            for (int ii = 0; ii < 2; ++ii) {
                float s = 0.0f;
#pragma unroll
                for (int j = 0; j < 8; ++j) s += Pr[ii][j] * qdx[j];
                cv[ii] = 0.02f * s;
            }
            c2[r] = pack2(cv[0], cv[1]);
        }
    }

    // ---- Seed u with iteration 1: u1 = clip(c)  (u0 = 0) ----
    {
        float* uw = ubuf;  // buffer 0
#pragma unroll
        for (int r = 0; r < ROWS; ++r) {
            float lo, hi;
            unpack2(c2[r], lo, hi);
            unsigned long long w = pack2(clip1(lo), clip1(hi));
            *reinterpret_cast<unsigned long long*>(uw + r * MDIM + m0) = w;
        }
    }
    __syncthreads();

    const unsigned long long* __restrict__ G2 =
        reinterpret_cast<const unsigned long long*>(g_G);

    int cur = 0;
    for (int it = 0; it < 99; ++it) {
        unsigned long long a[ROWS];
#pragma unroll
        for (int r = 0; r < ROWS; ++r) a[r] = c2[r];

        const float* ub = ubuf + cur * SMEM_U;

        // double-buffered G prefetch (4 k-rows ahead)
        unsigned long long g0, g1, g2, g3, h0, h1, h2, h3;
        g0 = G2[0 * 256 + tid];
        g1 = G2[1 * 256 + tid];
        g2 = G2[2 * 256 + tid];
        g3 = G2[3 * 256 + tid];

#pragma unroll 2
        for (int kb = 0; kb < 128; ++kb) {
            int kp = (kb < 127) ? (4 * kb + 4) : 0;   // guarded prefetch
            h0 = G2[(kp + 0) * 256 + tid];
            h1 = G2[(kp + 1) * 256 + tid];
            h2 = G2[(kp + 2) * 256 + tid];
            h3 = G2[(kp + 3) * 256 + tid];

            const float* ubk = ub + 4 * kb;
#pragma unroll
            for (int r = 0; r < ROWS; ++r) {
                float4 u4 = *reinterpret_cast<const float4*>(ubk + r * MDIM);
                a[r] = fma2(g0, pack_dup(u4.x), a[r]);
                a[r] = fma2(g1, pack_dup(u4.y), a[r]);
                a[r] = fma2(g2, pack_dup(u4.z), a[r]);
                a[r] = fma2(g3, pack_dup(u4.w), a[r]);
            }
            g0 = h0; g1 = h1; g2 = h2; g3 = h3;
        }

        // clip + write to the other buffer
        int nxt = cur ^ 1;
        float* uw = ubuf + nxt * SMEM_U;
#pragma unroll
        for (int r = 0; r < ROWS; ++r) {
            float lo, hi;
            unpack2(a[r], lo, hi);
            unsigned long long w = pack2(clip1(lo), clip1(hi));
            *reinterpret_cast<unsigned long long*>(uw + r * MDIM + m0) = w;
        }
        __syncthreads();
        cur = nxt;
    }

    // ---- write result (coalesced; tail rows clamped -> duplicate identical writes) ----
    const float* uf = ubuf + cur * SMEM_U;
    for (int idx = tid; idx < ROWS * MDIM; idx += THREADS) {
        int r = idx >> 9;          // / 512
        int m = idx & (MDIM - 1);
        int b = row0 + r;
        if (b > BATCH - 1) b = BATCH - 1;
        out[(long)b * MDIM + m] = uf[idx];
    }
}

extern "C" void kernel_launch(void* const* d_in, const int* in_sizes, int n_in,
                              void* d_out, int out_size) {
    // inputs: x0 (unused), xref, H, Phi, Q
    const float* xref = (const float*)d_in[1];
    const float* H    = (const float*)d_in[2];
    const float* Phi  = (const float*)d_in[3];
    const float* Q    = (const float*)d_in[4];
    float* out = (float*)d_out;

    cudaFuncSetAttribute(mpc_kernel,
                         cudaFuncAttributeMaxDynamicSharedMemorySize,
                         2 * SMEM_U * (int)sizeof(float));

    init_G_kernel<<<MDIM, MDIM>>>(H);
    mpc_kernel<<<CTAS, THREADS, 2 * SMEM_U * sizeof(float)>>>(xref, Phi, Q, out);
}

// round 13
// speedup vs baseline: 3.4533x; 1.6920x over previous
#include <cuda_runtime.h>
#include <cuda_fp16.h>
#include <cstdint>

// LinearMPC: u' = clip(G u + c), G = I - 0.01 H (512x512), batch 2048, 100 iters.
// Legacy tensor-core version (compute_103-safe: mma.sync m16n8k16 fp16, ldmatrix,
// clusters). 32 batch tiles x 64 rows; cluster of 4 CTAs per tile, each CTA owns
// 128 of the 512 output columns. fp16 hi/lo split of G and u, 3 MMA terms, fp32
// accumulate. G pre-packed fragment-major in gmem (one LDG.128 per A fragment,
// L1/L2 cached). u exchanged via double-buffered gmem scratch with __stcg/__ldcg
// (L2-coherent; inline cluster barrier does not flush L1, so L1 is bypassed).
// R11 fix: reload_u trip count was t<8 (refreshed only 16/64 batch rows -> 0.85
// rel_err); full tile is 8192 uint4 -> t<32.

#define MDIM 512
#define BATCH 2048
#define TILE_B 64
#define CLUSTER 4
#define NCTAS 128                  // 32 tiles * 4
#define NTHREADS 256               // 8 warps: mw = wid&3 (m32), nw = wid>>2 (n32)
#define XREF_STRIDE 520
#define ITERS 99                   // u1 = clip(c) seeded analytically

#define U_PITCH 520                // halves per u row (512 + 8 pad): conflict-free ldmatrix
#define CS_PITCH 132               // floats per c row (128 + 4 pad)

// SMEM layout (bytes)
#define SM_UHI 0
#define SM_ULO (TILE_B * U_PITCH * 2)              // 66560
#define SM_CS  (2 * TILE_B * U_PITCH * 2)          // 133120
#define SM_TOTAL (SM_CS + TILE_B * CS_PITCH * 4)   // 166912

// Fragment-packed G: [slice(4)][mtile(8)][t... index below], halves
__device__ __half g_Afrag[512 * 512 * 2];          // 1 MB
__device__ unsigned int g_scr[2][BATCH * MDIM];    // packed (lo16<<16)|hi16

// Pack G into per-thread A-fragment layout:
// frag id = ((slice*8 + mtile)*2 + p)*32 + s ; 512B per frag (32 lanes x 16B)
__global__ void init_G_kernel(const float* __restrict__ H) {
    int m = blockIdx.x;            // output row
    int k = threadIdx.x;           // K index
    float g = -0.01f * H[m * MDIM + k];
    if (m == k) g += 1.0f;
    __half hi = __float2half(g);
    __half lo = __float2half(g - __half2float(hi));
    int slice = m >> 7, mloc = m & 127, mtile = mloc >> 4, r = mloc & 15;
    int s = k >> 4, kin = k & 15;
    int L = (r & 7) * 4 + ((kin & 7) >> 1);
    int reg = (r >> 3) + 2 * (kin >> 3);
    int hf = kin & 1;
#pragma unroll
    for (int p = 0; p < 2; ++p) {
        long idx = ((((long)((slice * 8 + mtile) * 2 + p)) * 32 + s) * 32 + L) * 8
                   + reg * 2 + hf;
        g_Afrag[idx] = p ? lo : hi;
    }
}

// ---------------- helpers ----------------
__device__ __forceinline__ uint32_t smem_u32(const void* p) {
    uint32_t a;
    asm("{ .reg .u64 t; cvta.to.shared.u64 t, %1; cvt.u32.u64 %0, t; }"
        : "=r"(a) : "l"(p));
    return a;
}
__device__ __forceinline__ uint32_t cluster_rank() {
    uint32_t r; asm("mov.u32 %0, %%cluster_ctarank;" : "=r"(r)); return r;
}
#define CLUSTER_SYNC() do {                                           \
    asm volatile("barrier.cluster.arrive.aligned;" ::: "memory");     \
    asm volatile("barrier.cluster.wait.aligned;" ::: "memory"); } while (0)

#define LDM_X4(r0, r1, r2, r3, addr) \
    asm volatile("ldmatrix.sync.aligned.m8n8.x4.shared.b16 {%0,%1,%2,%3}, [%4];" \
        : "=r"(r0), "=r"(r1), "=r"(r2), "=r"(r3) : "r"(addr))

#define MMA16816(d, a, b0, b1) \
    asm volatile("mma.sync.aligned.m16n8k16.row.col.f32.f16.f16.f32 " \
        "{%0,%1,%2,%3}, {%4,%5,%6,%7}, {%8,%9}, {%0,%1,%2,%3};" \
        : "+f"((d)[0]), "+f"((d)[1]), "+f"((d)[2]), "+f"((d)[3]) \
        : "r"((a).x), "r"((a).y), "r"((a).z), "r"((a).w), "r"(b0), "r"(b1))

__device__ __forceinline__ float clip1(float x) {
    return fminf(fmaxf(x, -1.0f), 1.0f);
}
__device__ __forceinline__ unsigned int pack_split_h(float v) {
    __half hi = __float2half(v);
    __half lo = __float2half(v - __half2float(hi));
    return ((unsigned int)__half_as_ushort(lo) << 16) |
           (unsigned int)__half_as_ushort(hi);
}

// reload: gmem scratch (packed hi|lo) -> smem uhi/ulo [n][k] pitch U_PITCH halves
// Full tile = 64 n x 512 k words = 8192 uint4.
__device__ __forceinline__ void reload_u(char* smem, const unsigned int* scr_tile,
                                         int tid) {
    const uint4* src = (const uint4*)scr_tile;
#pragma unroll 8
    for (int t = 0; t < 32; ++t) {
        int idx = tid + t * NTHREADS;            // 0..8191
        uint4 q = __ldcg(src + idx);
        int n = idx >> 7, k = (idx & 127) * 4;
        uint32_t off = (uint32_t)(n * (U_PITCH * 2) + k * 2);
        unsigned long long h =
            (unsigned long long)(q.x & 0xFFFF) |
            ((unsigned long long)(q.y & 0xFFFF) << 16) |
            ((unsigned long long)(q.z & 0xFFFF) << 32) |
            ((unsigned long long)(q.w & 0xFFFF) << 48);
        unsigned long long l =
            (unsigned long long)(q.x >> 16) |
            ((unsigned long long)(q.y >> 16) << 16) |
            ((unsigned long long)(q.z >> 16) << 32) |
            ((unsigned long long)(q.w >> 16) << 48);
        *(unsigned long long*)(smem + SM_UHI + off) = h;
        *(unsigned long long*)(smem + SM_ULO + off) = l;
    }
}

extern "C" __global__ void __launch_bounds__(NTHREADS, 1) __cluster_dims__(CLUSTER, 1, 1)
mpc_mma_kernel(const float* __restrict__ xref,
               const float* __restrict__ Phi,
               const float* __restrict__ Q,
               float* __restrict__ out) {
    extern __shared__ char smem[];
    const uint32_t sb = smem_u32(smem);
    const int tid = threadIdx.x;
    const int wid = tid >> 5;
    const int lane = tid & 31;
    const int mw = wid & 3;                  // m position: rows mw*32..+31 of slice
    const int nw = wid >> 2;                 // n position: batch cols nw*32..+31
    const int slice = (int)cluster_rank();   // output column slice 0..3
    const int tile = blockIdx.x >> 2;        // batch tile 0..31

    // ---- c_s[n][m_loc] = 0.02 * (Phi[kblk] Q dx_b)[i] for this slice ----
    {
        float* cs = (float*)(smem + SM_CS);
#pragma unroll
        for (int t = 0; t < 4; ++t) {
            int p = tid + t * NTHREADS;       // 0..1023
            int b = p >> 4;                   // 0..63
            int kbl = p & 15;                 // 0..15 (local m block of 8)
            int kblk = slice * 16 + kbl;
            const float* xr = xref + (long)(tile * TILE_B + b) * XREF_STRIDE;
            float dx[8];
#pragma unroll
            for (int l = 0; l < 8; ++l)
                dx[l] = xr[kblk * 8 + l] - xr[l];
            float qdx[8];
#pragma unroll
            for (int j = 0; j < 8; ++j) {
                float s = 0.0f;
#pragma unroll
                for (int l = 0; l < 8; ++l) s += Q[j * 8 + l] * dx[l];
                qdx[j] = s;
            }
#pragma unroll
            for (int i = 0; i < 8; ++i) {
                float s = 0.0f;
#pragma unroll
                for (int j = 0; j < 8; ++j) s += Phi[kblk * 64 + i * 8 + j] * qdx[j];
                cs[b * CS_PITCH + kbl * 8 + i] = 0.02f * s;
            }
        }
    }
    __syncthreads();

    // ---- seed u1 = clip(c) into scratch buf 0 ----
    {
        const float* cs = (const float*)(smem + SM_CS);
        unsigned int* scr = g_scr[0] + (long)(tile * TILE_B) * MDIM;
#pragma unroll
        for (int t = 0; t < 32; ++t) {
            int e = tid + t * NTHREADS;        // 0..8191
            int b = e >> 7, ml = e & 127;
            __stcg(&scr[b * MDIM + slice * 128 + ml],
                   pack_split_h(clip1(cs[b * CS_PITCH + ml])));
        }
    }
    __threadfence();
    CLUSTER_SYNC();
    reload_u(smem, g_scr[0] + (long)(tile * TILE_B) * MDIM, tid);
    __syncthreads();

    // ---- precompute A-frag gmem base and B ldmatrix smem addresses ----
    const uint4* gA = (const uint4*)g_Afrag;
    // frag uint4 index = (((slice*8 + mw*2 + t)*2 + p)*32 + s)*32 + lane
    const int baseA = ((slice * 8 + mw * 2) * 2) * 32 * 32 + lane;
    // t stride = 2048 uint4; p stride = 1024; s stride = 32

    // B ldmatrix: lane q = lane/8, rr = lane%8; row = (q>>1)*8 + rr, koff = (q&1)*8
    const int q = lane >> 3, rr = lane & 7;
    const int brow = (q >> 1) * 8 + rr;
    const int bkoff = (q & 1) * 8;
    uint32_t bH0 = sb + SM_UHI + (uint32_t)((nw * 32 + brow) * (U_PITCH * 2) + bkoff * 2);
    uint32_t bH1 = bH0 + 16 * (U_PITCH * 2);
    uint32_t bL0 = bH0 + (SM_ULO - SM_UHI);
    uint32_t bL1 = bH1 + (SM_ULO - SM_UHI);

    const float* cs = (const float*)(smem + SM_CS);
    const int g = lane >> 2, cq = lane & 3;   // D frag: row g(+8), cols 2cq(+1)

    for (int it = 0; it < ITERS; ++it) {
        float D[2][4][4];
#pragma unroll
        for (int t = 0; t < 2; ++t)
#pragma unroll
            for (int nt = 0; nt < 4; ++nt)
#pragma unroll
                for (int e = 0; e < 4; ++e) D[t][nt][e] = 0.0f;

        uint32_t aH0 = bH0, aH1 = bH1, aL0 = bL0, aL1 = bL1;

#pragma unroll 2
        for (int s = 0; s < 32; ++s) {
            // A fragments: t0/t1 x hi/lo (coalesced LDG.128, L1/L2 cached)
            uint4 Ah0 = __ldg(gA + baseA + s * 32);
            uint4 Ah1 = __ldg(gA + baseA + 2048 + s * 32);
            uint4 Al0 = __ldg(gA + baseA + 1024 + s * 32);
            uint4 Al1 = __ldg(gA + baseA + 3072 + s * 32);
            // B fragments: hi/lo x 2 n-tile pairs
            uint32_t Bh[8], Bl[8];
            LDM_X4(Bh[0], Bh[1], Bh[2], Bh[3], aH0);
            LDM_X4(Bh[4], Bh[5], Bh[6], Bh[7], aH1);
            LDM_X4(Bl[0], Bl[1], Bl[2], Bl[3], aL0);
            LDM_X4(Bl[4], Bl[5], Bl[6], Bl[7], aL1);
            aH0 += 32; aH1 += 32; aL0 += 32; aL1 += 32;

            // term 1: Ghi * uhi
#pragma unroll
            for (int nt = 0; nt < 4; ++nt) {
                MMA16816(D[0][nt], Ah0, Bh[nt * 2], Bh[nt * 2 + 1]);
                MMA16816(D[1][nt], Ah1, Bh[nt * 2], Bh[nt * 2 + 1]);
            }
            // term 2: Ghi * ulo
#pragma unroll
            for (int nt = 0; nt < 4; ++nt) {
                MMA16816(D[0][nt], Ah0, Bl[nt * 2], Bl[nt * 2 + 1]);
                MMA16816(D[1][nt], Ah1, Bl[nt * 2], Bl[nt * 2 + 1]);
            }
            // term 3: Glo * uhi
#pragma unroll
            for (int nt = 0; nt < 4; ++nt) {
                MMA16816(D[0][nt], Al0, Bh[nt * 2], Bh[nt * 2 + 1]);
                MMA16816(D[1][nt], Al1, Bh[nt * 2], Bh[nt * 2 + 1]);
            }
        }

        // ---- epilogue: add c, clip, emit ----
        const bool last = (it == ITERS - 1);
        int nb = (it + 1) & 1;
        unsigned int* scr = g_scr[nb] + (long)(tile * TILE_B) * MDIM;
#pragma unroll
        for (int t = 0; t < 2; ++t) {
#pragma unroll
            for (int nt = 0; nt < 4; ++nt) {
                int m0 = mw * 32 + t * 16 + g;        // local m (0..127)
                int n0 = nw * 32 + nt * 8 + 2 * cq;   // local n (0..63)
#pragma unroll
                for (int e = 0; e < 4; ++e) {
                    int m = m0 + (e >> 1) * 8;
                    int n = n0 + (e & 1);
                    float v = clip1(D[t][nt][e] + cs[n * CS_PITCH + m]);
                    if (last) {
                        out[(long)(tile * TILE_B + n) * MDIM + slice * 128 + m] = v;
                    } else {
                        __stcg(&scr[(long)n * MDIM + slice * 128 + m],
                               pack_split_h(v));
                    }
                }
            }
        }

        if (!last) {
            __threadfence();
            CLUSTER_SYNC();
            reload_u(smem, g_scr[nb] + (long)(tile * TILE_B) * MDIM, tid);
            __syncthreads();
        }
    }
}

extern "C" void kernel_launch(void* const* d_in, const int* in_sizes, int n_in,
                              void* d_out, int out_size) {
    // inputs: x0 (unused), xref, H, Phi, Q
    const float* xref = (const float*)d_in[1];
    const float* H    = (const float*)d_in[2];
    const float* Phi  = (const float*)d_in[3];
    const float* Q    = (const float*)d_in[4];
    float* out = (float*)d_out;

    cudaFuncSetAttribute(mpc_mma_kernel,
                         cudaFuncAttributeMaxDynamicSharedMemorySize, SM_TOTAL);

    init_G_kernel<<<MDIM, MDIM>>>(H);
    mpc_mma_kernel<<<NCTAS, NTHREADS, SM_TOTAL>>>(xref, Phi, Q, out);
}

// round 15
// speedup vs baseline: 4.3553x; 1.2612x over previous
#include <cuda_runtime.h>
#include <cuda_fp16.h>
#include <cstdint>

// LinearMPC: u' = clip(G u + c), G = I - 0.01 H (512x512), batch 2048, 100 iters.
// mma.sync m16n8k16 fp16 hi/lo split (3 terms), fp32 accumulate.
// R13: TILE_B 64->32, grid 128->256 (2 CTAs/SM from different clusters) so the
// serial exchange/sync phase of one CTA overlaps the MMA phase of the other.
// 8 warps = 8 distinct m-tiles (no A duplication across warps).

#define MDIM 512
#define BATCH 2048
#define TILE_B 32
#define CLUSTER 4
#define NCTAS 256                  // 64 tiles * 4
#define NTHREADS 256               // 8 warps, warp w owns m-tile w (16 rows)
#define XREF_STRIDE 520
#define ITERS 99                   // u1 = clip(c) seeded analytically

#define U_PITCH 520                // halves per u row (512 + 8 pad)
#define CS_PITCH 132               // floats per c row (128 + 4 pad)

// SMEM layout (bytes)
#define SM_UHI 0
#define SM_ULO (TILE_B * U_PITCH * 2)              // 33280
#define SM_CS  (2 * TILE_B * U_PITCH * 2)          // 66560
#define SM_TOTAL (SM_CS + TILE_B * CS_PITCH * 4)   // 83456

// Fragment-packed G: frag id = ((slice*8 + mtile)*2 + p)*32 + s; 512B per frag
__device__ __half g_Afrag[512 * 512 * 2];          // 1 MB
__device__ unsigned int g_scr[2][BATCH * MDIM];    // packed (lo16<<16)|hi16

__global__ void init_G_kernel(const float* __restrict__ H) {
    int m = blockIdx.x;            // output row
    int k = threadIdx.x;           // K index
    float g = -0.01f * H[m * MDIM + k];
    if (m == k) g += 1.0f;
    __half hi = __float2half(g);
    __half lo = __float2half(g - __half2float(hi));
    int slice = m >> 7, mloc = m & 127, mtile = mloc >> 4, r = mloc & 15;
    int s = k >> 4, kin = k & 15;
    int L = (r & 7) * 4 + ((kin & 7) >> 1);
    int reg = (r >> 3) + 2 * (kin >> 3);
    int hf = kin & 1;
#pragma unroll
    for (int p = 0; p < 2; ++p) {
        long idx = ((((long)((slice * 8 + mtile) * 2 + p)) * 32 + s) * 32 + L) * 8
                   + reg * 2 + hf;
        g_Afrag[idx] = p ? lo : hi;
    }
}

// ---------------- helpers ----------------
__device__ __forceinline__ uint32_t smem_u32(const void* p) {
    uint32_t a;
    asm("{ .reg .u64 t; cvta.to.shared.u64 t, %1; cvt.u32.u64 %0, t; }"
        : "=r"(a) : "l"(p));
    return a;
}
__device__ __forceinline__ uint32_t cluster_rank() {
    uint32_t r; asm("mov.u32 %0, %%cluster_ctarank;" : "=r"(r)); return r;
}
#define CLUSTER_SYNC() do {                                           \
    asm volatile("barrier.cluster.arrive.aligned;" ::: "memory");     \
    asm volatile("barrier.cluster.wait.aligned;" ::: "memory"); } while (0)

#define LDM_X4(r0, r1, r2, r3, addr) \
    asm volatile("ldmatrix.sync.aligned.m8n8.x4.shared.b16 {%0,%1,%2,%3}, [%4];" \
        : "=r"(r0), "=r"(r1), "=r"(r2), "=r"(r3) : "r"(addr))

#define MMA16816(d, a, b0, b1) \
    asm volatile("mma.sync.aligned.m16n8k16.row.col.f32.f16.f16.f32 " \
        "{%0,%1,%2,%3}, {%4,%5,%6,%7}, {%8,%9}, {%0,%1,%2,%3};" \
        : "+f"((d)[0]), "+f"((d)[1]), "+f"((d)[2]), "+f"((d)[3]) \
        : "r"((a).x), "r"((a).y), "r"((a).z), "r"((a).w), "r"(b0), "r"(b1))

__device__ __forceinline__ float clip1(float x) {
    return fminf(fmaxf(x, -1.0f), 1.0f);
}
__device__ __forceinline__ unsigned int pack_split_h(float v) {
    __half hi = __float2half(v);
    __half lo = __float2half(v - __half2float(hi));
    return ((unsigned int)__half_as_ushort(lo) << 16) |
           (unsigned int)__half_as_ushort(hi);
}

// reload: gmem scratch (packed hi|lo) -> smem uhi/ulo [n][k], U_PITCH halves.
// Full tile = 32 n x 512 k words = 4096 uint4.
__device__ __forceinline__ void reload_u(char* smem, const unsigned int* scr_tile,
                                         int tid) {
    const uint4* src = (const uint4*)scr_tile;
#pragma unroll 8
    for (int t = 0; t < 16; ++t) {
        int idx = tid + t * NTHREADS;            // 0..4095
        uint4 q = __ldcg(src + idx);
        int n = idx >> 7, k = (idx & 127) * 4;
        uint32_t off = (uint32_t)(n * (U_PITCH * 2) + k * 2);
        unsigned long long h =
            (unsigned long long)(q.x & 0xFFFF) |
            ((unsigned long long)(q.y & 0xFFFF) << 16) |
            ((unsigned long long)(q.z & 0xFFFF) << 32) |
            ((unsigned long long)(q.w & 0xFFFF) << 48);
        unsigned long long l =
            (unsigned long long)(q.x >> 16) |
            ((unsigned long long)(q.y >> 16) << 16) |
            ((unsigned long long)(q.z >> 16) << 32) |
            ((unsigned long long)(q.w >> 16) << 48);
        *(unsigned long long*)(smem + SM_UHI + off) = h;
        *(unsigned long long*)(smem + SM_ULO + off) = l;
    }
}

extern "C" __global__ void __launch_bounds__(NTHREADS, 2) __cluster_dims__(CLUSTER, 1, 1)
mpc_mma_kernel(const float* __restrict__ xref,
               const float* __restrict__ Phi,
               const float* __restrict__ Q,
               float* __restrict__ out) {
    extern __shared__ char smem[];
    const uint32_t sb = smem_u32(smem);
    const int tid = threadIdx.x;
    const int wid = tid >> 5;                // m-tile index 0..7 (16 m rows each)
    const int lane = tid & 31;
    const int slice = (int)cluster_rank();   // output column slice 0..3
    const int tile = blockIdx.x >> 2;        // batch tile 0..63

    // ---- c_s[n][m_loc] = 0.02 * (Phi[kblk] Q dx_b)[i] for this slice ----
    {
        float* cs = (float*)(smem + SM_CS);
#pragma unroll
        for (int t = 0; t < 2; ++t) {
            int p = tid + t * NTHREADS;       // 0..511
            int b = p >> 4;                   // 0..31
            int kbl = p & 15;                 // 0..15
            int kblk = slice * 16 + kbl;
            const float* xr = xref + (long)(tile * TILE_B + b) * XREF_STRIDE;
            float dx[8];
#pragma unroll
            for (int l = 0; l < 8; ++l)
                dx[l] = xr[kblk * 8 + l] - xr[l];
            float qdx[8];
#pragma unroll
            for (int j = 0; j < 8; ++j) {
                float s = 0.0f;
#pragma unroll
                for (int l = 0; l < 8; ++l) s += Q[j * 8 + l] * dx[l];
                qdx[j] = s;
            }
#pragma unroll
            for (int i = 0; i < 8; ++i) {
                float s = 0.0f;
#pragma unroll
                for (int j = 0; j < 8; ++j) s += Phi[kblk * 64 + i * 8 + j] * qdx[j];
                cs[b * CS_PITCH + kbl * 8 + i] = 0.02f * s;
            }
        }
    }
    __syncthreads();

    // ---- seed u1 = clip(c) into scratch buf 0 ----
    {
        const float* cs = (const float*)(smem + SM_CS);
        unsigned int* scr = g_scr[0] + (long)(tile * TILE_B) * MDIM;
#pragma unroll
        for (int t = 0; t < 16; ++t) {
            int e = tid + t * NTHREADS;        // 0..4095
            int b = e >> 7, ml = e & 127;
            __stcg(&scr[b * MDIM + slice * 128 + ml],
                   pack_split_h(clip1(cs[b * CS_PITCH + ml])));
        }
    }
    __threadfence();
    CLUSTER_SYNC();
    reload_u(smem, g_scr[0] + (long)(tile * TILE_B) * MDIM, tid);
    __syncthreads();

    // ---- A-frag gmem base: frag uint4 idx = (((slice*8+wid)*2 + p)*32 + s)*32 + lane
    const uint4* gA = (const uint4*)g_Afrag;
    const int baseA = ((slice * 8 + wid) * 2) * 1024 + lane;  // p stride 1024, s stride 32

    // B ldmatrix addresses: lane q = lane/8, rr = lane%8
    const int q = lane >> 3, rr = lane & 7;
    const int brow = (q >> 1) * 8 + rr;
    const int bkoff = (q & 1) * 8;
    uint32_t bH0 = sb + SM_UHI + (uint32_t)(brow * (U_PITCH * 2) + bkoff * 2);
    uint32_t bH1 = bH0 + 16 * (U_PITCH * 2);
    uint32_t bL0 = bH0 + (SM_ULO - SM_UHI);
    uint32_t bL1 = bH1 + (SM_ULO - SM_UHI);

    const float* cs = (const float*)(smem + SM_CS);
    const int g = lane >> 2, cq = lane & 3;   // D frag: row g(+8), cols 2cq(+1)

    for (int it = 0; it < ITERS; ++it) {
        float D[4][4];
#pragma unroll
        for (int nt = 0; nt < 4; ++nt)
#pragma unroll
            for (int e = 0; e < 4; ++e) D[nt][e] = 0.0f;

        uint32_t aH0 = bH0, aH1 = bH1, aL0 = bL0, aL1 = bL1;

#pragma unroll 4
        for (int s = 0; s < 32; ++s) {
            uint4 Ah = __ldg(gA + baseA + s * 32);           // hi fragment
            uint4 Al = __ldg(gA + baseA + 1024 + s * 32);    // lo fragment
            uint32_t Bh[8], Bl[8];
            LDM_X4(Bh[0], Bh[1], Bh[2], Bh[3], aH0);
            LDM_X4(Bh[4], Bh[5], Bh[6], Bh[7], aH1);
            LDM_X4(Bl[0], Bl[1], Bl[2], Bl[3], aL0);
            LDM_X4(Bl[4], Bl[5], Bl[6], Bl[7], aL1);
            aH0 += 32; aH1 += 32; aL0 += 32; aL1 += 32;

#pragma unroll
            for (int nt = 0; nt < 4; ++nt)
                MMA16816(D[nt], Ah, Bh[nt * 2], Bh[nt * 2 + 1]);   // Ghi*uhi
#pragma unroll
            for (int nt = 0; nt < 4; ++nt)
                MMA16816(D[nt], Ah, Bl[nt * 2], Bl[nt * 2 + 1]);   // Ghi*ulo
#pragma unroll
            for (int nt = 0; nt < 4; ++nt)
                MMA16816(D[nt], Al, Bh[nt * 2], Bh[nt * 2 + 1]);   // Glo*uhi
        }

        // ---- epilogue: add c, clip, emit ----
        const bool last = (it == ITERS - 1);
        int nb = (it + 1) & 1;
        unsigned int* scr = g_scr[nb] + (long)(tile * TILE_B) * MDIM;
        const int m0 = wid * 16 + g;                 // local m base (0..127)
#pragma unroll
        for (int nt = 0; nt < 4; ++nt) {
            int n0 = nt * 8 + 2 * cq;                // local n (0..31)
#pragma unroll
            for (int e = 0; e < 4; ++e) {
                int m = m0 + (e >> 1) * 8;
                int n = n0 + (e & 1);
                float v = clip1(D[nt][e] + cs[n * CS_PITCH + m]);
                if (last) {
                    out[(long)(tile * TILE_B + n) * MDIM + slice * 128 + m] = v;
                } else {
                    __stcg(&scr[(long)n * MDIM + slice * 128 + m],
                           pack_split_h(v));
                }
            }
        }

        if (!last) {
            __threadfence();
            CLUSTER_SYNC();
            reload_u(smem, g_scr[nb] + (long)(tile * TILE_B) * MDIM, tid);
            __syncthreads();
        }
    }
}

extern "C" void kernel_launch(void* const* d_in, const int* in_sizes, int n_in,
                              void* d_out, int out_size) {
    // inputs: x0 (unused), xref, H, Phi, Q
    const float* xref = (const float*)d_in[1];
    const float* H    = (const float*)d_in[2];
    const float* Phi  = (const float*)d_in[3];
    const float* Q    = (const float*)d_in[4];
    float* out = (float*)d_out;

    cudaFuncSetAttribute(mpc_mma_kernel,
                         cudaFuncAttributeMaxDynamicSharedMemorySize, SM_TOTAL);

    init_G_kernel<<<MDIM, MDIM>>>(H);
    mpc_mma_kernel<<<NCTAS, NTHREADS, SM_TOTAL>>>(xref, Phi, Q, out);
}